// round 4
// baseline (speedup 1.0000x reference)
#include <cuda_runtime.h>

namespace {
constexpr int B   = 4;
constexpr int C   = 32;
constexpr int IMG = 256 * 256;
constexpr int RES = 128;
constexpr int M   = RES * RES;        // 16384 per batch
constexpr int VS  = 64, VT = 32;
constexpr int MV  = VS * VS * VT;     // 131072 per batch

constexpr size_t OFF_VID  = (size_t)B * M * 3;              // 196608
constexpr size_t OFF_FEAT = OFF_VID + (size_t)B * 3 * MV;   // 1769472

constexpr int K1_VID_BLOCKS = 128;
constexpr int K1_PRE_BLOCKS = 8;
constexpr int K2_MAIN_BLOCKS = 512;   // 128 points per block (2 threads/point)
constexpr int K2_ASM_BLOCKS  = 512;

struct Tap { int o0, o1, o2, o3; float w0, w1, w2, w3; };

__device__ __forceinline__ Tap make_tap(float gx, float gy) {
    Tap t;
    float x = fmaf(gx, 128.f, 127.5f);
    float y = fmaf(gy, 128.f, 127.5f);
    float xf = floorf(x), yf = floorf(y);
    int x0 = (int)xf, y0 = (int)yf;
    float fx = x - xf, fy = y - yf;
    int x1 = x0 + 1, y1 = y0 + 1;
    float vx0 = ((unsigned)x0 < 256u) ? 1.f : 0.f;
    float vx1 = ((unsigned)x1 < 256u) ? 1.f : 0.f;
    float vy0 = ((unsigned)y0 < 256u) ? 1.f : 0.f;
    float vy1 = ((unsigned)y1 < 256u) ? 1.f : 0.f;
    int cx0 = min(max(x0, 0), 255), cx1 = min(max(x1, 0), 255);
    int cy0 = min(max(y0, 0), 255), cy1 = min(max(y1, 0), 255);
    t.o0 = cy0 * 256 + cx0;  t.o1 = cy0 * 256 + cx1;
    t.o2 = cy1 * 256 + cx0;  t.o3 = cy1 * 256 + cx1;
    float wx0 = 1.f - fx, wx1 = fx, wy0 = 1.f - fy, wy1 = fy;
    t.w0 = wy0 * wx0 * vy0 * vx0;
    t.w1 = wy0 * wx1 * vy0 * vx1;
    t.w2 = wy1 * wx0 * vy1 * vx0;
    t.w3 = wy1 * wx1 * vy1 * vx1;
    return t;
}

__device__ __forceinline__ int get_axid(const float* cb) {
    int axid = 0; float best = cb[0];
    if (cb[1] > best) { best = cb[1]; axid = 1; }
    if (cb[2] > best) axid = 2;
    return axid;
}
} // namespace

// Scratch
__device__ float g_D[4 * 2 * 36 * 128];        // [b][axis][o(pad36)][idx]
__device__ float g_A0[3 * 4 * 64 * 64];        // [rgb][b][j][i]
__device__ float g_A1[3 * 4 * 64 * 32];        // [rgb][b][i][k]
__device__ float g_A2[3 * 4 * 64 * 32];        // [rgb][b][j][k]

// ---------------------------------------------------------------------------
// Kernel 1: blocks [0,128) video per-plane RGB tables (staging depth 16),
//           blocks [128,136) 1D-plane 35-vec precompute.
// ---------------------------------------------------------------------------
__global__ __launch_bounds__(256) void prep_kernel(
    const float* __restrict__ planes, const float* __restrict__ c,
    const float* __restrict__ Wd)
{
    if (blockIdx.x < K1_VID_BLOCKS) {
        __shared__ float4 sW3[96];
        for (int t = threadIdx.x; t < 96; t += 256)
            sW3[t] = make_float4(Wd[t * 35 + 0], Wd[t * 35 + 1], Wd[t * 35 + 2], 0.f);
        __syncthreads();

        int tid = blockIdx.x * 256 + threadIdx.x;
        int b = tid >> 13;
        int r = tid & 8191;

        const float* cb = c + b * 6;
        float x0 = fmaf(cb[4], 2.f, -1.f);
        float y0 = fmaf(cb[5], 2.f, -1.f);

        int p; float gx, gy; int didx; float* dbase; int dstride;
        if (r < 4096) {                     // plane0: (X(i), Y(j)) -> [b][j][i]
            int i = r & 63, j = r >> 6;
            p = 0;
            gx = x0 + (float)i * (2.f / 63.f);
            gy = y0 + (float)j * (2.f / 63.f);
            dbase = g_A0; dstride = 4 * 64 * 64;
            didx = (b * 64 + j) * 64 + i;
        } else if (r < 6144) {              // plane1: (X(i), Z(k)) -> [b][i][k]
            int rr = r - 4096;
            int i = rr & 63, k = rr >> 6;
            p = 1;
            gx = x0 + (float)i * (2.f / 63.f);
            gy = fmaf((float)k, 2.f / 31.f, -1.f);
            dbase = g_A1; dstride = 4 * 64 * 32;
            didx = (b * 64 + i) * 32 + k;
        } else {                            // plane2: (Z(k), Y(j)) -> [b][j][k]
            int rr = r - 6144;
            int k = rr & 31, j = rr >> 5;
            p = 2;
            gx = fmaf((float)k, 2.f / 31.f, -1.f);
            gy = y0 + (float)j * (2.f / 63.f);
            dbase = g_A2; dstride = 4 * 64 * 32;
            didx = (b * 64 + j) * 32 + k;
        }

        Tap T = make_tap(gx, gy);
        float a0 = 0.f, a1 = 0.f, a2 = 0.f;
        const float* bp = planes + ((size_t)b * 3 + p) * C * IMG;
        for (int cbase = 0; cbase < 32; cbase += 16) {
            float v0[16], v1[16], v2[16], v3[16];
#pragma unroll
            for (int cc = 0; cc < 16; cc++) {
                const float* img = bp + (cbase + cc) * IMG;
                v0[cc] = __ldg(img + T.o0); v1[cc] = __ldg(img + T.o1);
                v2[cc] = __ldg(img + T.o2); v3[cc] = __ldg(img + T.o3);
            }
#pragma unroll
            for (int cc = 0; cc < 16; cc++) {
                float f = T.w0 * v0[cc] + T.w1 * v1[cc] + T.w2 * v2[cc] + T.w3 * v3[cc];
                float4 w = sW3[p * 32 + cbase + cc];
                a0 = fmaf(f, w.x, a0);
                a1 = fmaf(f, w.y, a1);
                a2 = fmaf(f, w.z, a2);
            }
        }
        dbase[0 * dstride + didx] = a0;
        dbase[1 * dstride + didx] = a1;
        dbase[2 * dstride + didx] = a2;
    } else {
        // ---- 1D precompute: block = (b, axis); thread = (half, idx) ----
        __shared__ float sWp[32 * 36];
        __shared__ float sP[128 * 37];

        int gid = blockIdx.x - K1_VID_BLOCKS;
        int b = gid >> 1;
        int axis = gid & 1;

        const float* cb = c + b * 6;
        int axid = get_axid(cb);
        float tt = fmaf(cb[3], 2.f, -1.f);

        int p; bool g_is_x;
        if (axis == 0) { p = (axid == 2) ? 1 : 0; g_is_x = (axid != 0); }
        else           { p = (axid == 0) ? 1 : 2; g_is_x = (axid == 1); }

        for (int t = threadIdx.x; t < 32 * 36; t += 256) {
            int k = t / 36, o = t - k * 36;
            sWp[t] = (o < 35) ? Wd[(p * 32 + k) * 35 + o] : 0.f;
        }
        __syncthreads();

        int idx = threadIdx.x & 127;
        int half = threadIdx.x >> 7;

        float g = fmaf((float)idx, 2.f / 127.f, -1.f);
        float gx = g_is_x ? g : tt;
        float gy = g_is_x ? tt : g;
        Tap T = make_tap(gx, gy);

        float acc[35];
#pragma unroll
        for (int o = 0; o < 35; o++) acc[o] = 0.f;

        const float* bp = planes + ((size_t)b * 3 + p) * C * IMG;
        {
            int cbase = half * 16;
            float v0[16], v1[16], v2[16], v3[16];
#pragma unroll
            for (int cc = 0; cc < 16; cc++) {
                const float* img = bp + (cbase + cc) * IMG;
                v0[cc] = __ldg(img + T.o0); v1[cc] = __ldg(img + T.o1);
                v2[cc] = __ldg(img + T.o2); v3[cc] = __ldg(img + T.o3);
            }
#pragma unroll
            for (int cc = 0; cc < 16; cc++) {
                float f = T.w0 * v0[cc] + T.w1 * v1[cc] + T.w2 * v2[cc] + T.w3 * v3[cc];
                const float4* wr = reinterpret_cast<const float4*>(&sWp[(cbase + cc) * 36]);
#pragma unroll
                for (int q = 0; q < 9; q++) {
                    float4 w4 = wr[q];
                    if (4 * q + 0 < 35) acc[4 * q + 0] = fmaf(f, w4.x, acc[4 * q + 0]);
                    if (4 * q + 1 < 35) acc[4 * q + 1] = fmaf(f, w4.y, acc[4 * q + 1]);
                    if (4 * q + 2 < 35) acc[4 * q + 2] = fmaf(f, w4.z, acc[4 * q + 2]);
                    if (4 * q + 3 < 35) acc[4 * q + 3] = fmaf(f, w4.w, acc[4 * q + 3]);
                }
            }
        }

        if (half == 1) {
#pragma unroll
            for (int o = 0; o < 35; o++) sP[idx * 37 + o] = acc[o];
        }
        __syncthreads();
        if (half == 0) {
            float* dst = g_D + (size_t)(b * 2 + axis) * 36 * 128 + idx;
#pragma unroll
            for (int o = 0; o < 35; o++) dst[o * 128] = acc[o] + sP[idx * 37 + o];
        }
    }
}

// ---------------------------------------------------------------------------
// Kernel 2: blocks [0,512) main path (2 threads per point, shfl reduce),
//           blocks [512,1024) video assembly.
// ---------------------------------------------------------------------------
__global__ __launch_bounds__(256, 3) void render_kernel(
    const float* __restrict__ planes, const float* __restrict__ c,
    const float* __restrict__ Wd, const float* __restrict__ bd,
    float* __restrict__ out)
{
    if (blockIdx.x < K2_MAIN_BLOCKS) {
        __shared__ float sWp[32 * 36];
        __shared__ float sB[36];

        // 128 points per block; thread pair = lanes (k, k+16) within a warp
        int lane = threadIdx.x & 31;
        int sub  = lane & 15;
        int half = lane >> 4;                    // 0/1 -> channels [0,16)/[16,32)
        int pt_in_blk = (threadIdx.x >> 5) * 16 + sub;

        int pi = blockIdx.x * 128 + pt_in_blk;
        int b = pi >> 14;
        int t = pi & (M - 1);

        const float* cb = c + b * 6;
        int axid = get_axid(cb);
        int p2 = (axid == 0) ? 2 : ((axid == 1) ? 1 : 0);

        for (int tt = threadIdx.x; tt < 32 * 36; tt += 256) {
            int k = tt / 36, o = tt - k * 36;
            sWp[tt] = (o < 35) ? Wd[(p2 * 32 + k) * 35 + o] : 0.f;
        }
        if (threadIdx.x < 36)
            sB[threadIdx.x] = (threadIdx.x < 35) ? bd[threadIdx.x] : 0.f;
        __syncthreads();

        int i, j;
        if (axid == 0) { i = t >> 7; j = t & 127; }
        else           { i = t & 127; j = t >> 7; }
        float gi = fmaf((float)i, 2.f / 127.f, -1.f);
        float gj = fmaf((float)j, 2.f / 127.f, -1.f);
        float gx, gy;
        if (axid == 0) { gx = gj; gy = gi; }
        else           { gx = gi; gy = gj; }

        Tap T = make_tap(gx, gy);

        float acc[35];
        if (half == 0) {
            const float* Di = g_D + (size_t)(b * 2 + 0) * 36 * 128 + i;
            const float* Dj = g_D + (size_t)(b * 2 + 1) * 36 * 128 + j;
#pragma unroll
            for (int o = 0; o < 35; o++)
                acc[o] = sB[o] + __ldg(Di + o * 128) + __ldg(Dj + o * 128);
        } else {
#pragma unroll
            for (int o = 0; o < 35; o++) acc[o] = 0.f;
        }

        const float* bp = planes + ((size_t)b * 3 + p2) * C * IMG;
        int chbase = half * 16;
        for (int r = 0; r < 2; r++) {
            int cbase = chbase + r * 8;
            float v0[8], v1[8], v2[8], v3[8];
#pragma unroll
            for (int cc = 0; cc < 8; cc++) {
                const float* img = bp + (cbase + cc) * IMG;
                v0[cc] = __ldg(img + T.o0); v1[cc] = __ldg(img + T.o1);
                v2[cc] = __ldg(img + T.o2); v3[cc] = __ldg(img + T.o3);
            }
#pragma unroll
            for (int cc = 0; cc < 8; cc++) {
                float f = T.w0 * v0[cc] + T.w1 * v1[cc] + T.w2 * v2[cc] + T.w3 * v3[cc];
                const float4* wr = reinterpret_cast<const float4*>(&sWp[(cbase + cc) * 36]);
#pragma unroll
                for (int q = 0; q < 9; q++) {
                    float4 w4 = wr[q];
                    if (4 * q + 0 < 35) acc[4 * q + 0] = fmaf(f, w4.x, acc[4 * q + 0]);
                    if (4 * q + 1 < 35) acc[4 * q + 1] = fmaf(f, w4.y, acc[4 * q + 1]);
                    if (4 * q + 2 < 35) acc[4 * q + 2] = fmaf(f, w4.z, acc[4 * q + 2]);
                    if (4 * q + 3 < 35) acc[4 * q + 3] = fmaf(f, w4.w, acc[4 * q + 3]);
                }
            }
        }

        // pairwise reduce halves
#pragma unroll
        for (int o = 0; o < 35; o++)
            acc[o] += __shfl_xor_sync(0xffffffffu, acc[o], 16);

        if (half == 0) {
            int m_out = (axid == 0) ? t : (i * 128 + j);
            size_t co = ((size_t)b * M + m_out) * 3;
            out[co + 0] = acc[0]; out[co + 1] = acc[1]; out[co + 2] = acc[2];

            float* fo = out + OFF_FEAT + ((size_t)b * M + m_out) * 32;
#pragma unroll
            for (int q = 0; q < 8; q++) {
                float4 v = make_float4(acc[3 + 4 * q], acc[4 + 4 * q],
                                       acc[5 + 4 * q], acc[6 + 4 * q]);
                reinterpret_cast<float4*>(fo)[q] = v;
            }
        }
    } else {
        // ---- video assembly: thread handles 4 consecutive k ----
        int tid = (blockIdx.x - K2_MAIN_BLOCKS) * 256 + threadIdx.x;
        int k4 = (tid & 7) << 2;
        int j = (tid >> 3) & 63;
        int i = (tid >> 9) & 63;
        int b = tid >> 15;

        size_t base = OFF_VID + (size_t)b * 3 * MV + (size_t)i * (VS * VT) + (size_t)j * VT + k4;
#pragma unroll
        for (int rgb = 0; rgb < 3; rgb++) {
            float a0 = g_A0[(size_t)(rgb * 4 + b) * 4096 + j * 64 + i];
            const float4 a1 = *reinterpret_cast<const float4*>(
                &g_A1[(size_t)(rgb * 4 + b) * 2048 + i * 32 + k4]);
            const float4 a2 = *reinterpret_cast<const float4*>(
                &g_A2[(size_t)(rgb * 4 + b) * 2048 + j * 32 + k4]);
            float bias = __ldg(bd + rgb);
            float4 v;
            v.x = bias + a0 + a1.x + a2.x;
            v.y = bias + a0 + a1.y + a2.y;
            v.z = bias + a0 + a1.z + a2.z;
            v.w = bias + a0 + a1.w + a2.w;
            *reinterpret_cast<float4*>(&out[base + (size_t)rgb * MV]) = v;
        }
    }
}

extern "C" void kernel_launch(void* const* d_in, const int* in_sizes, int n_in,
                              void* d_out, int out_size) {
    const float* planes = (const float*)d_in[0];
    const float* c      = (const float*)d_in[1];
    const float* Wd     = (const float*)d_in[2];
    const float* bd     = (const float*)d_in[3];
    float* out = (float*)d_out;

    prep_kernel<<<K1_VID_BLOCKS + K1_PRE_BLOCKS, 256>>>(planes, c, Wd);
    render_kernel<<<K2_MAIN_BLOCKS + K2_ASM_BLOCKS, 256>>>(planes, c, Wd, bd, out);
}